// round 9
// baseline (speedup 1.0000x reference)
#include <cuda_runtime.h>
#include <cuda_fp16.h>

#define GROWS 1028
#define GCOLS 1028
#define NCELL (GROWS * GCOLS)

// Full-stencil layout: g_st[r*GCOLS+c] = 16 fp16 values = the whole 4x4
// stencil anchored at (r,c): rows r..r+3, cols c..c+3. 32 bytes, 32B-aligned
// -> never crosses a 128B line. Table: 1028*1028*32B = 33.8 MB (L2-resident).
struct __align__(32) Stencil32 { uint4 half_[2]; };  // half_[0]=rows 0-1, half_[1]=rows 2-3
__device__ Stencil32 g_st[NCELL];

__global__ void expand_kernel(const float* __restrict__ coeffs) {
    // one thread per (cell, half): writes one uint4 (8 fp16 = 2 rows x 4 cols)
    int idx = blockIdx.x * blockDim.x + threadIdx.x;
    if (idx >= NCELL * 2) return;
    int h = idx & 1;
    int cell = idx >> 1;
    int r = cell / GCOLS;
    int c = cell - r * GCOLS;
    int c1 = min(c + 1, GCOLS - 1);
    int c2 = min(c + 2, GCOLS - 1);
    int c3 = min(c + 3, GCOLS - 1);
    const float* rowA = coeffs + min(r + 2 * h,     GROWS - 1) * GCOLS;
    const float* rowB = coeffs + min(r + 2 * h + 1, GROWS - 1) * GCOLS;

    __half2 v[4];
    v[0] = __floats2half2_rn(__ldg(rowA + c),  __ldg(rowA + c1));
    v[1] = __floats2half2_rn(__ldg(rowA + c2), __ldg(rowA + c3));
    v[2] = __floats2half2_rn(__ldg(rowB + c),  __ldg(rowB + c1));
    v[3] = __floats2half2_rn(__ldg(rowB + c2), __ldg(rowB + c3));
    reinterpret_cast<uint4*>(g_st)[idx] = *reinterpret_cast<uint4*>(v);
}

// 2 lanes per point: lane j in {0,1} handles stencil rows {2j, 2j+1}.
// Both lanes' 16B gathers land in the SAME 128B line (32B-aligned stencil)
// -> one L1tex wavefront per point instead of two.
__global__ void __launch_bounds__(256) spline_kernel(
    const float2* __restrict__ x, float* __restrict__ out, int n)
{
    int tid = blockIdx.x * blockDim.x + threadIdx.x;
    int i = tid >> 1;   // point index
    int j = tid & 1;    // stencil half
    if (i >= n) return;

    float2 p = __ldg(&x[i]);  // lane pair reads same 8B (one 128B line / 16 pts)
    float xn0 = fmaf(p.x, 1024.0f, -0.5f);
    float xn1 = fmaf(p.y, 1024.0f, -0.5f);
    bool valid = (xn0 > -2.0f) && (xn0 < 1024.0f) &&
                 (xn1 > -2.0f) && (xn1 < 1024.0f);

    float P0 = floorf(xn0), P1 = floorf(xn1);
    float t0 = xn0 - P0,    t1 = xn1 - P1;

    // Column weights (all 4).
    float o1 = 1.0f - t1;
    float t1sq = t1 * t1, o1sq = o1 * o1;
    float w1a = o1sq * o1;
    float w1b = fmaf(fmaf(3.0f, t1, -6.0f), t1sq, 4.0f);
    float w1c = fmaf(fmaf(3.0f, o1, -6.0f), o1sq, 4.0f);
    float w1d = t1sq * t1;

    // Row weights for this lane's two rows.
    // rows: w0 = {(1-t)^3, g(t), g(1-t), t^3}, g(u)=(3u-6)u^2+4
    float o0 = 1.0f - t0;
    float t0sq = t0 * t0, o0sq = o0 * o0;
    float w0a = o0sq * o0;
    float w0b = fmaf(fmaf(3.0f, t0, -6.0f), t0sq, 4.0f);
    float w0c = fmaf(fmaf(3.0f, o0, -6.0f), o0sq, 4.0f);
    float w0d = t0sq * t0;
    float wr0 = j ? w0c : w0a;
    float wr1 = j ? w0d : w0b;

    int r0 = (int)P0 + 1;
    int c0 = (int)P1 + 1;
    r0 = min(max(r0, 0), GROWS - 4);
    c0 = min(max(c0, 0), GCOLS - 4);
    int base = r0 * GCOLS + c0;

    // Lane pair loads the two 16B halves of one 32B stencil (same 128B line).
    const uint4* tab = reinterpret_cast<const uint4*>(g_st);
    uint4 v = __ldg(tab + 2 * base + j);

    __half2* vh = reinterpret_cast<__half2*>(&v);
    float2 rAlo = __half22float2(vh[0]), rAhi = __half22float2(vh[1]);
    float2 rBlo = __half22float2(vh[2]), rBhi = __half22float2(vh[3]);

    float sA = fmaf(rAlo.x, w1a, fmaf(rAlo.y, w1b, fmaf(rAhi.x, w1c, rAhi.y * w1d)));
    float sB = fmaf(rBlo.x, w1a, fmaf(rBlo.y, w1b, fmaf(rBhi.x, w1c, rBhi.y * w1d)));

    float s = fmaf(sA, wr0, sB * wr1);
    s += __shfl_xor_sync(0xffffffffu, s, 1);

    if (j == 0) out[i] = valid ? s : 0.0f;
}

extern "C" void kernel_launch(void* const* d_in, const int* in_sizes, int n_in,
                              void* d_out, int out_size) {
    const float2* x = (const float2*)d_in[0];     // [N,2] float32
    const float* coeffs = (const float*)d_in[1];  // [1028,1028] float32
    float* out = (float*)d_out;                   // [N,1] float32
    int n = out_size;                             // 2097152

    int etotal = NCELL * 2;
    expand_kernel<<<(etotal + 255) / 256, 256>>>(coeffs);

    long threads = 2L * n;
    spline_kernel<<<(int)((threads + 255) / 256), 256>>>(x, out, n);
}

// round 14
// speedup vs baseline: 1.0708x; 1.0708x over previous
#include <cuda_runtime.h>
#include <cuda_fp16.h>

#define GROWS 1028
#define GCOLS 1028
#define NCELL (GROWS * GCOLS)

// Pair layout: g_pair[r*GCOLS+c] = 8 fp16 values
//   { coeffs[r, c..c+3], coeffs[r+1, c..c+3] }
// 16 bytes, 16B-aligned -> one LDG.128 fetches two stencil rows.
// Table: 1028*1028*16B = 16.9 MB -> kept in L2 via evict_last cache-hint policy.
struct __align__(16) Pair8 { __half2 h[4]; };
__device__ Pair8 g_pair[NCELL];

// Create an L2 "evict_last" access policy (once per thread; uniform-pipe cheap).
__device__ __forceinline__ unsigned long long mk_evict_last_policy() {
    unsigned long long pol;
    asm volatile("createpolicy.fractional.L2::evict_last.b64 %0, 1.0;" : "=l"(pol));
    return pol;
}

// 128-bit non-coherent load with cache-hint policy (legal encoding on sm_103a).
__device__ __forceinline__ uint4 ldg_table(const uint4* p, unsigned long long pol) {
    uint4 v;
    asm volatile("ld.global.nc.L2::cache_hint.v4.u32 {%0,%1,%2,%3}, [%4], %5;"
                 : "=r"(v.x), "=r"(v.y), "=r"(v.z), "=r"(v.w)
                 : "l"(p), "l"(pol));
    return v;
}

__global__ void expand_kernel(const float* __restrict__ coeffs) {
    int idx = blockIdx.x * blockDim.x + threadIdx.x;
    if (idx >= NCELL) return;
    int r = idx / GCOLS;
    int c = idx - r * GCOLS;
    int c1 = min(c + 1, GCOLS - 1);
    int c2 = min(c + 2, GCOLS - 1);
    int c3 = min(c + 3, GCOLS - 1);
    const float* row0 = coeffs + r * GCOLS;
    const float* row1 = coeffs + min(r + 1, GROWS - 1) * GCOLS;

    Pair8 v;
    v.h[0] = __floats2half2_rn(__ldg(row0 + c),  __ldg(row0 + c1));
    v.h[1] = __floats2half2_rn(__ldg(row0 + c2), __ldg(row0 + c3));
    v.h[2] = __floats2half2_rn(__ldg(row1 + c),  __ldg(row1 + c1));
    v.h[3] = __floats2half2_rn(__ldg(row1 + c2), __ldg(row1 + c3));
    g_pair[idx] = v;  // single 16B store
}

// Evaluate one point given its two stencil uint4s (already loaded).
__device__ __forceinline__ float eval_point(
    float xn0, float xn1, uint4 au, uint4 bu)
{
    float P0 = floorf(xn0), P1 = floorf(xn1);
    float t0 = xn0 - P0,    t1 = xn1 - P1;

    float o1 = 1.0f - t1;
    float t1sq = t1 * t1, o1sq = o1 * o1;
    float w1a = o1sq * o1;
    float w1b = fmaf(fmaf(3.0f, t1, -6.0f), t1sq, 4.0f);
    float w1c = fmaf(fmaf(3.0f, o1, -6.0f), o1sq, 4.0f);
    float w1d = t1sq * t1;

    float o0 = 1.0f - t0;
    float t0sq = t0 * t0, o0sq = o0 * o0;
    float w0a = o0sq * o0;
    float w0b = fmaf(fmaf(3.0f, t0, -6.0f), t0sq, 4.0f);
    float w0c = fmaf(fmaf(3.0f, o0, -6.0f), o0sq, 4.0f);
    float w0d = t0sq * t0;

    __half2* ah = reinterpret_cast<__half2*>(&au);
    __half2* bh = reinterpret_cast<__half2*>(&bu);
    float2 r0lo = __half22float2(ah[0]), r0hi = __half22float2(ah[1]);
    float2 r1lo = __half22float2(ah[2]), r1hi = __half22float2(ah[3]);
    float2 r2lo = __half22float2(bh[0]), r2hi = __half22float2(bh[1]);
    float2 r3lo = __half22float2(bh[2]), r3hi = __half22float2(bh[3]);

    float s0 = fmaf(r0lo.x, w1a, fmaf(r0lo.y, w1b, fmaf(r0hi.x, w1c, r0hi.y * w1d)));
    float s1 = fmaf(r1lo.x, w1a, fmaf(r1lo.y, w1b, fmaf(r1hi.x, w1c, r1hi.y * w1d)));
    float s2 = fmaf(r2lo.x, w1a, fmaf(r2lo.y, w1b, fmaf(r2hi.x, w1c, r2hi.y * w1d)));
    float s3 = fmaf(r3lo.x, w1a, fmaf(r3lo.y, w1b, fmaf(r3hi.x, w1c, r3hi.y * w1d)));

    return fmaf(s0, w0a, fmaf(s1, w0b, fmaf(s2, w0c, s3 * w0d)));
}

__device__ __forceinline__ int stencil_base(float xn0, float xn1) {
    int r0 = (int)floorf(xn0) + 1;
    int c0 = (int)floorf(xn1) + 1;
    r0 = min(max(r0, 0), GROWS - 4);
    c0 = min(max(c0, 0), GCOLS - 4);
    return r0 * GCOLS + c0;
}

// 2 points per thread: 4 independent stencil gathers in flight (MLP=4).
__global__ void __launch_bounds__(256) spline_kernel(
    const float4* __restrict__ x2, float2* __restrict__ out, int npair)
{
    int i = blockIdx.x * blockDim.x + threadIdx.x;
    if (i >= npair) return;

    unsigned long long pol = mk_evict_last_policy();

    float4 p = __ldcs(&x2[i]);  // streaming: don't evict the table

    float a0 = fmaf(p.x, 1024.0f, -0.5f);
    float a1 = fmaf(p.y, 1024.0f, -0.5f);
    float b0 = fmaf(p.z, 1024.0f, -0.5f);
    float b1 = fmaf(p.w, 1024.0f, -0.5f);

    bool va = (a0 > -2.0f) && (a0 < 1024.0f) && (a1 > -2.0f) && (a1 < 1024.0f);
    bool vb = (b0 > -2.0f) && (b0 < 1024.0f) && (b1 > -2.0f) && (b1 < 1024.0f);

    int baseA = stencil_base(a0, a1);
    int baseB = stencil_base(b0, b1);

    // Issue all 4 gathers before any math.
    const uint4* tab = reinterpret_cast<const uint4*>(g_pair);
    uint4 Aa = ldg_table(tab + baseA, pol);
    uint4 Ab = ldg_table(tab + baseA + 2 * GCOLS, pol);
    uint4 Ba = ldg_table(tab + baseB, pol);
    uint4 Bb = ldg_table(tab + baseB + 2 * GCOLS, pol);

    float ra = eval_point(a0, a1, Aa, Ab);
    float rb = eval_point(b0, b1, Ba, Bb);

    float2 o;
    o.x = va ? ra : 0.0f;
    o.y = vb ? rb : 0.0f;
    __stcs(&out[i], o);  // streaming store
}

extern "C" void kernel_launch(void* const* d_in, const int* in_sizes, int n_in,
                              void* d_out, int out_size) {
    const float4* x2 = (const float4*)d_in[0];    // [N/2] float4 (2 points each)
    const float* coeffs = (const float*)d_in[1];  // [1028,1028] float32
    float2* out = (float2*)d_out;                 // [N/2] float2
    int n = out_size;                             // 2097152 (even)
    int npair = n >> 1;

    expand_kernel<<<(NCELL + 255) / 256, 256>>>(coeffs);
    spline_kernel<<<(npair + 255) / 256, 256>>>(x2, out, npair);
}